// round 2
// baseline (speedup 1.0000x reference)
#include <cuda_runtime.h>
#include <cstdint>
#include <cstddef>

// ---------------- device scratch (no runtime allocs) ----------------
__device__ float g_att3[256 * 16384];
__device__ float g_att2[1024 * 16384];
__device__ float g_feat3[4 * 64 * 64 * 64];
__device__ float g_up3 [4 * 64 * 128 * 128];
__device__ float g_al2 [4 * 64 * 128 * 128];
__device__ float g_atr2[4 * 64 * 128 * 128];
__device__ float g_feat2[4 * 64 * 128 * 128];
__device__ float g_up2 [4 * 64 * 256 * 256];
__device__ float g_al1 [4 * 64 * 256 * 256];
__device__ float g_atr1[4 * 64 * 256 * 256];

// ---------------- windowed cross attention: 1 block / 8x8 window ----------------
// smem floats: xs,ys,qs,ks,vs = 64x65 each; wr = weights then attn rows (16640);
// mk = 64; bs = 900. total 38404 floats = 153616 B.
#define ATTN_SMEM_BYTES (38404 * 4)

__global__ __launch_bounds__(256) void attn_kernel(
    const float* __restrict__ ref, const float* __restrict__ ta,
    const float* __restrict__ qw, const float* __restrict__ qb,
    const float* __restrict__ kw, const float* __restrict__ kb,
    const float* __restrict__ vw, const float* __restrict__ vb,
    const float* __restrict__ pw, const float* __restrict__ pb,
    const float* __restrict__ btab,
    float* __restrict__ outA, float* __restrict__ attOut, int H, int W)
{
    extern __shared__ float sm[];
    float* xs = sm;          float* ys = sm + 4160;
    float* qs = sm + 8320;   float* ks = sm + 12480;
    float* vs = sm + 16640;  float* wr = sm + 20800;   // 16640 floats
    float* mk = sm + 37440;  float* bs = sm + 37504;   // 900

    const int tid = threadIdx.x;
    const int nwx = W >> 3, nwyx = (H >> 3) * nwx;
    const int win = blockIdx.x;
    const int b = win / nwyx, rw = win - b * nwyx;
    const int y0 = (rw / nwx) * 8, x0 = (rw % nwx) * 8;

    const float* refb = ref + (size_t)b * 64 * H * W;
    const float* tab  = ta  + (size_t)b * 64 * H * W;

    for (int e = tid; e < 4096; e += 256) {
        int c = e >> 6, n = e & 63;
        size_t gi = ((size_t)c * H + (y0 + (n >> 3))) * W + x0 + (n & 7);
        xs[n * 65 + c] = refb[gi];
        ys[n * 65 + c] = tab[gi];
    }
    {   // stage q|k|v weights
        const float4* q4 = (const float4*)qw;
        const float4* k4 = (const float4*)kw;
        const float4* v4 = (const float4*)vw;
        float4* w4 = (float4*)wr;
        for (int e = tid; e < 1024; e += 256) {
            w4[e] = q4[e]; w4[1024 + e] = k4[e]; w4[2048 + e] = v4[e];
        }
    }
    for (int e = tid; e < 900; e += 256) bs[e] = btab[e];
    __syncthreads();

    if (tid < 64) {
        float cnt = 0.f;
        #pragma unroll 8
        for (int c = 0; c < 64; c++) cnt += (xs[tid * 65 + c] > 0.95f) ? 0.f : 1.f;
        mk[tid] = cnt * (1.f / 64.f);
    }
    __syncthreads();
    for (int e = tid; e < 4096; e += 256) {
        int c = e >> 6, n = e & 63;
        xs[n * 65 + c] *= mk[n];
    }
    __syncthreads();

    const int n = tid & 63, g = tid >> 6, ck0 = g * 16;

    // Q,K,V GEMMs: out[n, ck0..ck0+15]
    #pragma unroll
    for (int which = 0; which < 3; which++) {
        const float* in  = (which == 0) ? xs : ys;
        const float* bia = (which == 0) ? qb : (which == 1) ? kb : vb;
        float* outp      = (which == 0) ? qs : (which == 1) ? ks : vs;
        const float4* w4 = (const float4*)(wr + which * 4096);
        float acc[16];
        #pragma unroll
        for (int i = 0; i < 16; i++) acc[i] = bia[ck0 + i];
        #pragma unroll 4
        for (int c4 = 0; c4 < 16; c4++) {
            float a0 = in[n*65 + c4*4 + 0], a1 = in[n*65 + c4*4 + 1];
            float a2 = in[n*65 + c4*4 + 2], a3 = in[n*65 + c4*4 + 3];
            #pragma unroll
            for (int i = 0; i < 16; i++) {
                float4 w = w4[(ck0 + i) * 16 + c4];
                acc[i] += a0*w.x + a1*w.y + a2*w.z + a3*w.w;
            }
        }
        float sc = (which == 0) ? 0.25f : 1.0f;
        #pragma unroll
        for (int i = 0; i < 16; i++) outp[n * 65 + ck0 + i] = acc[i] * sc;
    }
    __syncthreads();   // wr weights dead -> attn rows

    {   // scores + mask + bias + softmax, row (h=g, n) per thread
        float qrow[16];
        #pragma unroll
        for (int d = 0; d < 16; d++) qrow[d] = qs[n * 65 + ck0 + d];
        const float mn = mk[n];
        const int r1 = n >> 3, c1 = n & 7;
        float* arow = wr + tid * 65;
        for (int m = 0; m < 64; m++) {
            float s = 0.f;
            #pragma unroll
            for (int d = 0; d < 16; d++) s += qrow[d] * ks[m * 65 + ck0 + d];
            int rel = (r1 - (m >> 3) + 7) * 15 + (c1 - (m & 7) + 7);
            arow[m] = s * (mn * mk[m]) + bs[rel * 4 + g];
        }
        float mx = arow[0];
        for (int m = 1; m < 64; m++) mx = fmaxf(mx, arow[m]);
        float ssum = 0.f;
        for (int m = 0; m < 64; m++) { float e = __expf(arow[m] - mx); arow[m] = e; ssum += e; }
        float inv = 1.f / ssum;
        for (int m = 0; m < 64; m++) arow[m] *= inv;
    }
    __syncthreads();

    if (attOut) {
        float* ao = attOut + (size_t)win * 16384;
        for (int e = tid; e < 16384; e += 256)
            ao[e] = wr[(e >> 6) * 65 + (e & 63)];
    }

    {   // attn @ v -> qs (dead)
        float acc[16];
        #pragma unroll
        for (int i = 0; i < 16; i++) acc[i] = 0.f;
        const float* arow = wr + tid * 65;
        for (int m = 0; m < 64; m++) {
            float a = arow[m];
            #pragma unroll
            for (int i = 0; i < 16; i++) acc[i] += a * vs[m * 65 + ck0 + i];
        }
        #pragma unroll
        for (int i = 0; i < 16; i++) qs[n * 65 + ck0 + i] = acc[i];
    }
    __syncthreads();
    {   // stage pw into ks (dead)
        const float4* p4 = (const float4*)pw;
        float4* k4m = (float4*)ks;
        for (int e = tid; e < 1024; e += 256) k4m[e] = p4[e];
    }
    __syncthreads();
    {   // projection -> vs
        float acc[16];
        #pragma unroll
        for (int i = 0; i < 16; i++) acc[i] = pb[ck0 + i];
        const float4* w4 = (const float4*)ks;
        #pragma unroll 4
        for (int c4 = 0; c4 < 16; c4++) {
            float a0 = qs[n*65 + c4*4 + 0], a1 = qs[n*65 + c4*4 + 1];
            float a2 = qs[n*65 + c4*4 + 2], a3 = qs[n*65 + c4*4 + 3];
            #pragma unroll
            for (int i = 0; i < 16; i++) {
                float4 w = w4[(ck0 + i) * 16 + c4];
                acc[i] += a0*w.x + a1*w.y + a2*w.z + a3*w.w;
            }
        }
        #pragma unroll
        for (int i = 0; i < 16; i++) vs[n * 65 + ck0 + i] = acc[i];
    }
    __syncthreads();
    float* ob = outA + (size_t)b * 64 * H * W;
    for (int e = tid; e < 4096; e += 256) {
        int c = e >> 6, nn = e & 63;
        ob[((size_t)c * H + y0 + (nn >> 3)) * W + x0 + (nn & 7)] = vs[nn * 65 + c];
    }
}

// ---------------- attention transfer: 1 block / 16x16 fine window ----------------
#define ATR_SMEM_BYTES (20544 * 4)
__global__ __launch_bounds__(256) void atrans_kernel(
    const float* __restrict__ att, const float* __restrict__ ta,
    float* __restrict__ out, int H, int W)
{
    extern __shared__ float sm[];
    float* attm = sm;           // [64][65]
    float* wt   = sm + 4160;    // [64][256] then output staging
    const int tid = threadIdx.x;
    const int nwx = W >> 4, nwyx = (H >> 4) * nwx;
    const int win = blockIdx.x;
    const int b = win / nwyx, rw = win - b * nwyx;
    const int y0 = (rw / nwx) * 16, x0 = (rw % nwx) * 16;

    const float* ab = att + (size_t)win * 16384;
    for (int e = tid; e < 4096; e += 256) {
        float s = ab[e] + ab[e + 4096] + ab[e + 8192] + ab[e + 12288];
        attm[(e >> 6) * 65 + (e & 63)] = 0.25f * s;
    }
    const float* tb = ta + (size_t)b * 64 * H * W;
    for (int e = tid; e < 16384; e += 256) {
        int c = e >> 8, py = (e >> 4) & 15, px = e & 15;
        int m = (py >> 1) * 8 + (px >> 1);
        int f = ((py & 1) * 2 + (px & 1)) * 64 + c;
        wt[m * 256 + f] = tb[((size_t)c * H + y0 + py) * W + x0 + px];
    }
    __syncthreads();

    float res[64];
    #pragma unroll
    for (int i = 0; i < 64; i++) res[i] = 0.f;
    for (int m = 0; m < 64; m++) {
        float w = wt[m * 256 + tid];
        #pragma unroll
        for (int i = 0; i < 64; i++) res[i] += attm[i * 65 + m] * w;
    }
    __syncthreads();
    {
        int c = tid & 63, d = tid >> 6, dr = d >> 1, dc = d & 1;
        #pragma unroll
        for (int i = 0; i < 64; i++) {
            int py = (i >> 3) * 2 + dr, px = (i & 7) * 2 + dc;
            wt[c * 256 + py * 16 + px] = res[i];
        }
    }
    __syncthreads();
    float* ob = out + (size_t)b * 64 * H * W;
    for (int e = tid; e < 16384; e += 256) {
        int c = e >> 8, py = (e >> 4) & 15, px = e & 15;
        ob[((size_t)c * H + y0 + py) * W + x0 + px] = wt[e];
    }
}

// ---------------- 3x3 conv 192->64 + bias + lrelu ----------------
__global__ __launch_bounds__(256) void conv_kernel(
    const float* __restrict__ a, const float* __restrict__ u,
    const float* __restrict__ tr, const float* __restrict__ wgt,
    const float* __restrict__ bias, float* __restrict__ out, int H, int W)
{
    __shared__ __align__(16) float tile[16 * 10 * 34];
    __shared__ __align__(16) float ws[16 * 9 * 16];
    const int tid = threadIdx.x;
    const int tx0 = blockIdx.x * 32;
    const int nty = H / 8;
    const int b = blockIdx.y / nty;
    const int ty0 = (blockIdx.y % nty) * 8;
    const int oc0 = blockIdx.z * 16;
    const int px = tid & 31, py = tid >> 5;

    float acc[16];
    #pragma unroll
    for (int i = 0; i < 16; i++) acc[i] = 0.f;

    for (int cc = 0; cc < 12; cc++) {
        const int icg = cc * 16;
        const float* src = (icg < 64) ? a : (icg < 128) ? u : tr;
        const int icl = icg & 63;
        __syncthreads();
        for (int e = tid; e < 5440; e += 256) {
            int ic = e / 340, rem = e - ic * 340;
            int tyy = rem / 34, txx = rem - tyy * 34;
            int gy = ty0 + tyy - 1, gx = tx0 + txx - 1;
            float v = 0.f;
            if (gy >= 0 && gy < H && gx >= 0 && gx < W)
                v = src[(((size_t)b * 64 + icl + ic) * H + gy) * W + gx];
            tile[e] = v;
        }
        for (int e = tid; e < 2304; e += 256) {
            int oc = e & 15, r = e >> 4, ic = r / 9, p = r - ic * 9;
            ws[e] = wgt[(((size_t)(oc0 + oc)) * 192 + icg + ic) * 9 + p];
        }
        __syncthreads();
        for (int ic = 0; ic < 16; ic++) {
            const float* tp = &tile[ic * 340 + py * 34 + px];
            float v[9] = { tp[0], tp[1], tp[2], tp[34], tp[35], tp[36],
                           tp[68], tp[69], tp[70] };
            const float4* w4 = (const float4*)&ws[ic * 144];
            #pragma unroll
            for (int p = 0; p < 9; p++) {
                float vv = v[p];
                float4 w0 = w4[p*4+0], w1 = w4[p*4+1], w2 = w4[p*4+2], w3 = w4[p*4+3];
                acc[0]  += vv*w0.x; acc[1]  += vv*w0.y; acc[2]  += vv*w0.z; acc[3]  += vv*w0.w;
                acc[4]  += vv*w1.x; acc[5]  += vv*w1.y; acc[6]  += vv*w1.z; acc[7]  += vv*w1.w;
                acc[8]  += vv*w2.x; acc[9]  += vv*w2.y; acc[10] += vv*w2.z; acc[11] += vv*w2.w;
                acc[12] += vv*w3.x; acc[13] += vv*w3.y; acc[14] += vv*w3.z; acc[15] += vv*w3.w;
            }
        }
    }
    __syncthreads();
    #pragma unroll
    for (int i = 0; i < 16; i++) {
        float v = acc[i] + bias[oc0 + i];
        tile[(i * 8 + py) * 32 + px] = v > 0.f ? v : 0.1f * v;
    }
    __syncthreads();
    for (int e = tid; e < 4096; e += 256) {
        int oc = e >> 8, tyy = (e >> 5) & 7, txx = e & 31;
        out[(((size_t)b * 64 + oc0 + oc) * H + ty0 + tyy) * W + tx0 + txx] = tile[e];
    }
}

// ---------------- bilinear 2x upsample (half-pixel), optional lrelu on input ----
template <bool LR>
__global__ void upsample2x_kernel(const float* __restrict__ in,
                                  float* __restrict__ out, int H, int W)
{
    const int OW = W * 2, OH = H * 2;
    const size_t total = (size_t)256 * OH * OW;
    for (size_t idx = (size_t)blockIdx.x * blockDim.x + threadIdx.x;
         idx < total; idx += (size_t)gridDim.x * blockDim.x) {
        int ox = (int)(idx % OW);
        size_t r = idx / OW;
        int oy = (int)(r % OH);
        int ch = (int)(r / OH);
        float sy = oy * 0.5f - 0.25f, fy = floorf(sy), wy = sy - fy;
        int iy = (int)fy;
        int yA = iy < 0 ? 0 : iy, yB = (iy + 1 > H - 1) ? H - 1 : iy + 1;
        float sx = ox * 0.5f - 0.25f, fx = floorf(sx), wx = sx - fx;
        int ix = (int)fx;
        int xA = ix < 0 ? 0 : ix, xB = (ix + 1 > W - 1) ? W - 1 : ix + 1;
        const float* p = in + (size_t)ch * H * W;
        float v00 = p[(size_t)yA * W + xA], v01 = p[(size_t)yA * W + xB];
        float v10 = p[(size_t)yB * W + xA], v11 = p[(size_t)yB * W + xB];
        if (LR) {
            v00 = v00 > 0.f ? v00 : 0.1f * v00;
            v01 = v01 > 0.f ? v01 : 0.1f * v01;
            v10 = v10 > 0.f ? v10 : 0.1f * v10;
            v11 = v11 > 0.f ? v11 : 0.1f * v11;
        }
        float t0 = v00 + wx * (v01 - v00);
        float t1 = v10 + wx * (v11 - v10);
        out[idx] = t0 + wy * (t1 - t0);
    }
}

// -------------------------------- launch --------------------------------
extern "C" void kernel_launch(void* const* d_in, const int* in_sizes, int n_in,
                              void* d_out, int out_size)
{
    const float* ref1 = (const float*)d_in[0];
    const float* ref2 = (const float*)d_in[1];
    const float* ref3 = (const float*)d_in[2];
    const float* ta1  = (const float*)d_in[3];
    const float* ta2  = (const float*)d_in[4];
    const float* ta3  = (const float*)d_in[5];
    const float* qw   = (const float*)d_in[6];
    const float* qb   = (const float*)d_in[7];
    const float* kw   = (const float*)d_in[8];
    const float* kb   = (const float*)d_in[9];
    const float* vw   = (const float*)d_in[10];
    const float* vb   = (const float*)d_in[11];
    const float* pw   = (const float*)d_in[12];
    const float* pb   = (const float*)d_in[13];
    const float* btab = (const float*)d_in[14];
    const float* fcw  = (const float*)d_in[15];
    const float* fcb  = (const float*)d_in[16];
    float* out = (float*)d_out;

    cudaFuncSetAttribute(attn_kernel, cudaFuncAttributeMaxDynamicSharedMemorySize, ATTN_SMEM_BYTES);
    cudaFuncSetAttribute(atrans_kernel, cudaFuncAttributeMaxDynamicSharedMemorySize, ATR_SMEM_BYTES);

    float *att3, *att2, *feat3, *up3, *al2, *atr2, *feat2, *up2, *al1, *atr1;
    cudaGetSymbolAddress((void**)&att3,  g_att3);
    cudaGetSymbolAddress((void**)&att2,  g_att2);
    cudaGetSymbolAddress((void**)&feat3, g_feat3);
    cudaGetSymbolAddress((void**)&up3,   g_up3);
    cudaGetSymbolAddress((void**)&al2,   g_al2);
    cudaGetSymbolAddress((void**)&atr2,  g_atr2);
    cudaGetSymbolAddress((void**)&feat2, g_feat2);
    cudaGetSymbolAddress((void**)&up2,   g_up2);
    cudaGetSymbolAddress((void**)&al1,   g_al1);
    cudaGetSymbolAddress((void**)&atr1,  g_atr1);

    const int WW = 64 * 64;       // per-level q/k/v/p weight stride
    const int BT = 225 * 4;       // bias table stride
    const int FW = 64 * 192 * 9;  // conv weight stride

    // ---- level 3 (64x64, j=2) ----
    attn_kernel<<<256, 256, ATTN_SMEM_BYTES>>>(
        ref3, ta3, qw + 2*WW, qb + 2*64, kw + 2*WW, kb + 2*64,
        vw + 2*WW, vb + 2*64, pw + 2*WW, pb + 2*64, btab + 2*BT,
        feat3, att3, 64, 64);
    {
        size_t tot = (size_t)256 * 128 * 128;
        upsample2x_kernel<true><<<(int)((tot + 255) / 256), 256>>>(feat3, up3, 64, 64);
    }

    // ---- level 2 (128x128, j=1) ----
    attn_kernel<<<1024, 256, ATTN_SMEM_BYTES>>>(
        ref2, ta2, qw + WW, qb + 64, kw + WW, kb + 64,
        vw + WW, vb + 64, pw + WW, pb + 64, btab + BT,
        al2, att2, 128, 128);
    atrans_kernel<<<256, 256, ATR_SMEM_BYTES>>>(att3, ta2, atr2, 128, 128);
    conv_kernel<<<dim3(4, 64, 4), 256>>>(al2, up3, atr2, fcw + FW, fcb + 64, feat2, 128, 128);
    {
        size_t tot = (size_t)256 * 256 * 256;
        upsample2x_kernel<false><<<(int)((tot + 255) / 256), 256>>>(feat2, up2, 128, 128);
    }

    // ---- level 1 (256x256, j=0) ----
    attn_kernel<<<4096, 256, ATTN_SMEM_BYTES>>>(
        ref1, ta1, qw, qb, kw, kb, vw, vb, pw, pb, btab,
        al1, nullptr, 256, 256);
    atrans_kernel<<<1024, 256, ATR_SMEM_BYTES>>>(att2, ta1, atr1, 256, 256);
    conv_kernel<<<dim3(8, 128, 4), 256>>>(al1, up2, atr1, fcw, fcb, out, 256, 256);
}